// round 12
// baseline (speedup 1.0000x reference)
#include <cuda_runtime.h>
#include <cuda_bf16.h>
#include <cstdint>

#define TLEN  512
#define FDIM  1024
#define NW    8             // warps per block = time chunks
#define CHUNK (TLEN / NW)   // 64 timesteps per warp
#define U1    16            // phase-1 float2 load batch
#define U2    4             // phase-2 float2 batch, double-buffered
#define F2    (FDIM / 2)    // row stride in float2

typedef unsigned long long ull;

__device__ __forceinline__ float fast_sqrt(float a) {
    float r; asm("sqrt.approx.f32 %0, %1;" : "=f"(r) : "f"(a)); return r;
}
__device__ __forceinline__ float fast_tanh(float a) {
    float r; asm("tanh.approx.f32 %0, %1;" : "=f"(r) : "f"(a)); return r;
}
// ---- packed f32x2 (sm_100+) ----
__device__ __forceinline__ ull pack2(float lo, float hi) {
    ull r; asm("mov.b64 %0, {%1, %2};" : "=l"(r) : "f"(lo), "f"(hi)); return r;
}
__device__ __forceinline__ void unpack2(ull v, float& lo, float& hi) {
    asm("mov.b64 {%0, %1}, %2;" : "=f"(lo), "=f"(hi) : "l"(v));
}
__device__ __forceinline__ ull add2(ull a, ull b) {
    ull r; asm("add.rn.f32x2 %0, %1, %2;" : "=l"(r) : "l"(a), "l"(b)); return r;
}
__device__ __forceinline__ ull sub2(ull a, ull b) {
    ull r; asm("sub.rn.f32x2 %0, %1, %2;" : "=l"(r) : "l"(a), "l"(b)); return r;
}
__device__ __forceinline__ ull mul2(ull a, ull b) {
    ull r; asm("mul.rn.f32x2 %0, %1, %2;" : "=l"(r) : "l"(a), "l"(b)); return r;
}
__device__ __forceinline__ ull fma2(ull a, ull b, ull c) {
    ull r; asm("fma.rn.f32x2 %0, %1, %2, %3;" : "=l"(r) : "l"(a), "l"(b), "l"(c)); return r;
}

__global__ __launch_bounds__(NW * 32, 4)
void dyn_dense_kernel(const float* __restrict__ x, const float* __restrict__ ws,
                      const float* __restrict__ qs, const float* __restrict__ bias,
                      float* __restrict__ out)
{
    __shared__ float2 s_invc2[TLEN];               // (1/c, 1/c) pairs: LDS.64 -> packed operand
    __shared__ float2 sm_s[NW][32];                // per-chunk partials (float2 = 2 features)
    __shared__ float2 sm_m[NW][32];
    __shared__ float2 sm_q[NW][32];

    const int tid  = threadIdx.x;
    const int warp = tid >> 5;
    const int lane = tid & 31;

    #pragma unroll
    for (int i = tid; i < TLEN; i += NW * 32) {    // 256 threads, 2 entries each
        const float ic = 1.0f / (float)(i + 1);
        s_invc2[i] = make_float2(ic, ic);
    }

    // grid = B * (FDIM/64); block covers 64 consecutive f, 2 per thread
    const int fblk = blockIdx.x & (FDIM / 64 - 1);   // 16 f-tiles
    const int b    = blockIdx.x >> 4;
    const int f0   = fblk * 64 + lane * 2;

    const size_t colbase2 = ((size_t)b * TLEN * FDIM + (size_t)(warp * CHUNK) * FDIM + f0) >> 1;
    const float2* xp = (const float2*)x + colbase2;

    float2 bufA[U2], bufB[U2];

    // ---- Phase 1: per-chunk partials (sum, max, sumsq) over 64 steps ----
    // Warp NW-1's partials feed nobody (exclusive prefix) -> skip its pass.
    // Max identity 0.0f matches the Keras zero-init of the max state.
    if (warp < NW - 1) {
        float psx = 0.f, psy = 0.f, pmx = 0.f, pmy = 0.f, pqx = 0.f, pqy = 0.f;
        const float2* p = xp;
        #pragma unroll
        for (int t0 = 0; t0 < CHUNK; t0 += U1) {
            float2 xv[U1];
            #pragma unroll
            for (int u = 0; u < U1; u++)
                xv[u] = __ldg(p + u * F2);          // 16 LDG.64 in flight
            p += U1 * F2;
            #pragma unroll
            for (int u = 0; u < U1; u++) {
                psx += xv[u].x;                 psy += xv[u].y;
                pqx  = fmaf(xv[u].x, xv[u].x, pqx);
                pqy  = fmaf(xv[u].y, xv[u].y, pqy);
                pmx  = fmaxf(pmx, xv[u].x);     pmy  = fmaxf(pmy, xv[u].y);
            }
        }
        sm_s[warp][lane] = make_float2(psx, psy);
        sm_m[warp][lane] = make_float2(pmx, pmy);
        sm_q[warp][lane] = make_float2(pqx, pqy);
    }

    // prefetch first phase-2 batch before the barrier (L2-hot for warps 0..NW-2)
    #pragma unroll
    for (int u = 0; u < U2; u++)
        bufA[u] = __ldg(xp + u * F2);

    __syncthreads();

    // ---- Phase 2: exclusive prefix over earlier chunks ----
    float sx = 0.f, sy = 0.f, mx = 0.f, my = 0.f, ssx = 0.f, ssy = 0.f;
    #pragma unroll
    for (int w = 0; w < NW - 1; w++) {
        if (w < warp) {
            float2 a  = sm_s[w][lane]; sx += a.x;  sy += a.y;
            float2 mm = sm_m[w][lane]; mx = fmaxf(mx, mm.x); my = fmaxf(my, mm.y);
            float2 qv = sm_q[w][lane]; ssx += qv.x; ssy += qv.y;
        }
    }

    // per-aggregation weights (AGGS = sum,max,mean,var,std), packed per thread-pair
    const float2 w0 = __ldg((const float2*)(ws + 0 * FDIM + f0));
    const float2 w1 = __ldg((const float2*)(ws + 1 * FDIM + f0));
    const float2 w2 = __ldg((const float2*)(ws + 2 * FDIM + f0));
    const float2 w3 = __ldg((const float2*)(ws + 3 * FDIM + f0));
    const float2 w4 = __ldg((const float2*)(ws + 4 * FDIM + f0));
    const float2 q0 = __ldg((const float2*)(qs + 0 * FDIM + f0));
    const float2 q1 = __ldg((const float2*)(qs + 1 * FDIM + f0));
    const float2 bb = __ldg((const float2*)(bias + f0));

    const ull W0P = pack2(w0.x, w0.y);
    const ull W1P = pack2(w1.x, w1.y);
    const ull W2P = pack2(w2.x, w2.y);
    const ull W3P = pack2(w3.x, w3.y);
    const ull W4P = pack2(w4.x, w4.y);
    const ull Q0P = pack2(q0.x, q0.y);
    const ull Q1P = pack2(q1.x, q1.y);
    // fold exact eps-correction into bias (z-chain uses w3*(var+eps))
    const ull BZP  = pack2(fmaf(-w3.x, 1e-4f, bb.x), fmaf(-w3.y, 1e-4f, bb.y));
    const ull EPSP = pack2(1e-4f, 1e-4f);
    const ull ONEP = pack2(1.0f, 1.0f);

    const float c0 = (float)(warp * CHUNK);
    ull CPP = pack2(c0 + 1.0f, c0 + 1.0f);         // count, shared by the pair

    const float2* p = xp + U2 * F2;                // bufA covers steps 0..U2-1
    float2*       o = (float2*)out + colbase2;
    const float2* icp = &s_invc2[warp * CHUNK];

    // one packed scan step: 2 features of one timestep
    auto step = [&](float2 xt, int t) {
        // serial accumulators (scalar; FMNMX has no packed form)
        sx += xt.x;                      sy += xt.y;
        ssx = fmaf(xt.x, xt.x, ssx);     ssy = fmaf(xt.y, xt.y, ssy);
        mx  = fmaxf(mx, xt.x);           my  = fmaxf(my, xt.y);

        const ull SP  = pack2(sx, sy);
        const ull MP  = pack2(mx, my);
        const ull SSP = pack2(ssx, ssy);
        const ull ICP = *(const ull*)&icp[t];      // LDS.64 broadcast, pre-duplicated (ic,ic)

        const ull MEANP = mul2(SP, ICP);
        const ull T1P   = fma2(SSP, ICP, EPSP);    // ss/c + eps
        const ull M2P   = mul2(MEANP, MEANP);
        const ull VEPSP = sub2(T1P, M2P);          // var + eps

        float v0, v1; unpack2(VEPSP, v0, v1);
        const ull SDP = pack2(fast_sqrt(v0), fast_sqrt(v1));

        ull ZP = fma2(Q1P, CPP, Q0P);              // count polynomial
        ZP = fma2(ZP, CPP, BZP);                   // BZP holds eps fix
        ZP = fma2(W0P, SP,    ZP);
        ZP = fma2(W1P, MP,    ZP);
        ZP = fma2(W2P, MEANP, ZP);
        ZP = fma2(W3P, VEPSP, ZP);
        ZP = fma2(W4P, SDP,   ZP);
        CPP = add2(CPP, ONEP);

        float z0, z1; unpack2(ZP, z0, z1);
        float2 r; r.x = fast_tanh(z0); r.y = fast_tanh(z1);
        o[t * F2] = r;                             // STG.64
    };

    // double-buffered scan over this chunk; reloads are L2-hot
    #pragma unroll 2
    for (int t0 = 0; t0 < CHUNK; t0 += 2 * U2) {
        #pragma unroll
        for (int u = 0; u < U2; u++)
            bufB[u] = __ldg(p + u * F2);
        p += U2 * F2;
        #pragma unroll
        for (int u = 0; u < U2; u++)
            step(bufA[u], t0 + u);

        if (t0 + 2 * U2 < CHUNK) {
            #pragma unroll
            for (int u = 0; u < U2; u++)
                bufA[u] = __ldg(p + u * F2);
            p += U2 * F2;
        }
        #pragma unroll
        for (int u = 0; u < U2; u++)
            step(bufB[u], t0 + U2 + u);
    }
}

extern "C" void kernel_launch(void* const* d_in, const int* in_sizes, int n_in,
                              void* d_out, int out_size)
{
    const float* x    = (const float*)d_in[0];
    const float* ws   = (const float*)d_in[1];
    const float* qs   = (const float*)d_in[2];
    const float* bias = (const float*)d_in[3];
    float* out = (float*)d_out;

    const int grid = 32 * (FDIM / 64);   // B * 16 f-tiles = 512 blocks
    dyn_dense_kernel<<<grid, NW * 32>>>(x, ws, qs, bias, out);
}

// round 13
// speedup vs baseline: 1.0018x; 1.0018x over previous
#include <cuda_runtime.h>
#include <cuda_bf16.h>
#include <cstdint>

#define TLEN  512
#define FDIM  1024
#define NW    16            // warps per block = time chunks
#define CHUNK (TLEN / NW)   // 32 timesteps per warp
#define NPAIR (CHUNK / 2)   // 16 (t,t+1) pairs per warp
#define U1    8             // phase-1 rolling load batch

typedef unsigned long long ull;

__device__ __forceinline__ float fast_sqrt(float a) {
    float r; asm("sqrt.approx.f32 %0, %1;" : "=f"(r) : "f"(a)); return r;
}
__device__ __forceinline__ float fast_tanh(float a) {
    float r; asm("tanh.approx.f32 %0, %1;" : "=f"(r) : "f"(a)); return r;
}
// ---- packed f32x2 (sm_100+) ----
__device__ __forceinline__ ull pack2(float lo, float hi) {
    ull r; asm("mov.b64 %0, {%1, %2};" : "=l"(r) : "f"(lo), "f"(hi)); return r;
}
__device__ __forceinline__ void unpack2(ull v, float& lo, float& hi) {
    asm("mov.b64 {%0, %1}, %2;" : "=f"(lo), "=f"(hi) : "l"(v));
}
__device__ __forceinline__ ull add2(ull a, ull b) {
    ull r; asm("add.rn.f32x2 %0, %1, %2;" : "=l"(r) : "l"(a), "l"(b)); return r;
}
__device__ __forceinline__ ull sub2(ull a, ull b) {
    ull r; asm("sub.rn.f32x2 %0, %1, %2;" : "=l"(r) : "l"(a), "l"(b)); return r;
}
__device__ __forceinline__ ull mul2(ull a, ull b) {
    ull r; asm("mul.rn.f32x2 %0, %1, %2;" : "=l"(r) : "l"(a), "l"(b)); return r;
}
__device__ __forceinline__ ull fma2(ull a, ull b, ull c) {
    ull r; asm("fma.rn.f32x2 %0, %1, %2, %3;" : "=l"(r) : "l"(a), "l"(b), "l"(c)); return r;
}

// dynamic smem layout (72 KB):
//  [0)                     float2 sx2[NW][NPAIR][32]   64 KB  (x_t, x_{t+1}) pairs
//  [65536)                 float2 invc2[TLEN/2]         2 KB  (1/(2p+1), 1/(2p+2))
//  [67584)                 float  sm_s[NW][32]          2 KB
//  [69632)                 float  sm_m[NW][32]          2 KB
//  [71680)                 float  sm_q[NW][32]          2 KB
#define SMEM_BYTES (64*1024 + 2*1024 + 3*2*1024)

__global__ __launch_bounds__(NW * 32, 3)
void dyn_dense_kernel(const float* __restrict__ x, const float* __restrict__ ws,
                      const float* __restrict__ qs, const float* __restrict__ bias,
                      float* __restrict__ out)
{
    extern __shared__ char smem[];
    float2* sx2   = (float2*)smem;                       // [NW][NPAIR][32]
    float2* invc2 = (float2*)(smem + 65536);
    float*  sm_s  = (float*)(smem + 67584);
    float*  sm_m  = (float*)(smem + 69632);
    float*  sm_q  = (float*)(smem + 71680);

    const int tid  = threadIdx.x;
    const int warp = tid >> 5;
    const int lane = tid & 31;

    if (tid < TLEN / 2) {
        const float a = 1.0f / (float)(2 * tid + 1);
        const float bq = 1.0f / (float)(2 * tid + 2);
        invc2[tid] = make_float2(a, bq);
    }

    // grid = B * (FDIM/32); block covers 32 consecutive f, all of T
    const int fblk = blockIdx.x & (FDIM / 32 - 1);
    const int b    = blockIdx.x >> 5;
    const int f    = fblk * 32 + lane;

    const size_t colbase = (size_t)b * TLEN * FDIM + (size_t)(warp * CHUNK) * FDIM + f;
    const float* p = x + colbase;

    // ---- Phase 1: load chunk ONCE (rolling batch), stage (t,t+1) pairs to smem,
    //      accumulate per-chunk partials. Max identity 0.0f = Keras zero-init. ----
    float ps = 0.0f, pm = 0.0f, pq = 0.0f;
    float2* myrow = &sx2[(warp * NPAIR) * 32 + lane];    // stride 32 float2 per pair-slot
    #pragma unroll
    for (int t0 = 0; t0 < CHUNK; t0 += U1) {
        float xv[U1];
        #pragma unroll
        for (int u = 0; u < U1; u++)
            xv[u] = __ldg(p + u * FDIM);                 // 8 LDGs in flight
        p += U1 * FDIM;
        #pragma unroll
        for (int u = 0; u < U1; u += 2) {
            myrow[((t0 + u) >> 1) * 32] = make_float2(xv[u], xv[u + 1]);  // STS.64
            ps += xv[u];  ps += xv[u + 1];
            pq  = fmaf(xv[u], xv[u], pq);
            pq  = fmaf(xv[u + 1], xv[u + 1], pq);
            pm  = fmaxf(pm, xv[u]);
            pm  = fmaxf(pm, xv[u + 1]);
        }
    }
    sm_s[warp * 32 + lane] = ps;
    sm_m[warp * 32 + lane] = pm;
    sm_q[warp * 32 + lane] = pq;
    __syncthreads();

    // ---- Phase 2: exclusive prefix over earlier chunks ----
    float s = 0.0f, m = 0.0f, ss = 0.0f;
    #pragma unroll
    for (int w = 0; w < NW - 1; w++) {
        if (w < warp) {
            s  += sm_s[w * 32 + lane];
            m   = fmaxf(m, sm_m[w * 32 + lane]);
            ss += sm_q[w * 32 + lane];
        }
    }

    // per-aggregation weights (AGGS = sum,max,mean,var,std), duplicated packed
    const float w0 = __ldg(ws + 0 * FDIM + f);
    const float w1 = __ldg(ws + 1 * FDIM + f);
    const float w2 = __ldg(ws + 2 * FDIM + f);
    const float w3 = __ldg(ws + 3 * FDIM + f);
    const float w4 = __ldg(ws + 4 * FDIM + f);
    const float q0 = __ldg(qs + 0 * FDIM + f);
    const float q1 = __ldg(qs + 1 * FDIM + f);
    // fold exact eps-correction into bias (z-chain uses w3*(var+eps))
    const float bz = fmaf(-w3, 1e-4f, __ldg(bias + f));

    const ull W0P = pack2(w0, w0);
    const ull W1P = pack2(w1, w1);
    const ull W2P = pack2(w2, w2);
    const ull W3P = pack2(w3, w3);
    const ull W4P = pack2(w4, w4);
    const ull Q0P = pack2(q0, q0);
    const ull Q1P = pack2(q1, q1);
    const ull BZP = pack2(bz, bz);
    const ull EPSP = pack2(1e-4f, 1e-4f);
    const ull TWOP = pack2(2.0f, 2.0f);

    const float c0 = (float)(warp * CHUNK);
    ull CPP = pack2(c0 + 1.0f, c0 + 2.0f);               // counts of the (t, t+1) pair

    float* o = out + colbase;
    const float2* icp = &invc2[warp * NPAIR];

    // 16 packed pair-steps: serial state twice (exact), then packed z-chain
    #pragma unroll
    for (int sp = 0; sp < NPAIR; sp++) {
        const float2 xp2 = myrow[sp * 32];               // LDS.64: (x_t, x_{t+1})

        const float s1  = s  + xp2.x;                    // state after t
        const float ss1 = fmaf(xp2.x, xp2.x, ss);
        const float m1  = fmaxf(m, xp2.x);
        s  = s1 + xp2.y;                                 // state after t+1
        ss = fmaf(xp2.y, xp2.y, ss1);
        m  = fmaxf(m1, xp2.y);

        const ull SP  = pack2(s1, s);
        const ull MP  = pack2(m1, m);
        const ull SSP = pack2(ss1, ss);
        const ull ICP = *(const ull*)&icp[sp];           // LDS.64 broadcast (1/c_t, 1/c_{t+1})

        const ull MEANP = mul2(SP, ICP);
        const ull T1P   = fma2(SSP, ICP, EPSP);          // ss/c + eps
        const ull VEPSP = sub2(T1P, mul2(MEANP, MEANP)); // var + eps

        float v0, v1; unpack2(VEPSP, v0, v1);
        const ull SDP = pack2(fast_sqrt(v0), fast_sqrt(v1));

        ull ZP = fma2(Q1P, CPP, Q0P);                    // count polynomial
        ZP = fma2(ZP, CPP, BZP);                         // BZP holds eps fix
        ZP = fma2(W0P, SP,    ZP);
        ZP = fma2(W1P, MP,    ZP);
        ZP = fma2(W2P, MEANP, ZP);
        ZP = fma2(W3P, VEPSP, ZP);
        ZP = fma2(W4P, SDP,   ZP);
        CPP = add2(CPP, TWOP);

        float z0, z1; unpack2(ZP, z0, z1);
        o[(2 * sp)     * FDIM] = fast_tanh(z0);
        o[(2 * sp + 1) * FDIM] = fast_tanh(z1);
    }
}

extern "C" void kernel_launch(void* const* d_in, const int* in_sizes, int n_in,
                              void* d_out, int out_size)
{
    const float* x    = (const float*)d_in[0];
    const float* ws   = (const float*)d_in[1];
    const float* qs   = (const float*)d_in[2];
    const float* bias = (const float*)d_in[3];
    float* out = (float*)d_out;

    cudaFuncSetAttribute(dyn_dense_kernel,
                         cudaFuncAttributeMaxDynamicSharedMemorySize, SMEM_BYTES);

    const int grid = 32 * (FDIM / 32);   // B * 32 f-tiles = 1024 blocks
    dyn_dense_kernel<<<grid, NW * 32, SMEM_BYTES>>>(x, ws, qs, bias, out);
}

// round 14
// speedup vs baseline: 1.0573x; 1.0554x over previous
#include <cuda_runtime.h>
#include <cuda_bf16.h>
#include <cstdint>

#define TLEN  512
#define FDIM  1024
#define NW    16            // warps per block = time chunks
#define CHUNK (TLEN / NW)   // 32 timesteps per warp
#define NPAIR (CHUNK / 2)   // 16 (t,t+1) pairs per warp
#define SPAIR 8             // pairs staged in smem; rest re-read (L1/L2-hot)

typedef unsigned long long ull;

__device__ __forceinline__ float fast_sqrt(float a) {
    float r; asm("sqrt.approx.f32 %0, %1;" : "=f"(r) : "f"(a)); return r;
}
__device__ __forceinline__ float fast_tanh(float a) {
    float r; asm("tanh.approx.f32 %0, %1;" : "=f"(r) : "f"(a)); return r;
}
// ---- packed f32x2 (sm_100+) ----
__device__ __forceinline__ ull pack2(float lo, float hi) {
    ull r; asm("mov.b64 %0, {%1, %2};" : "=l"(r) : "f"(lo), "f"(hi)); return r;
}
__device__ __forceinline__ void unpack2(ull v, float& lo, float& hi) {
    asm("mov.b64 {%0, %1}, %2;" : "=f"(lo), "=f"(hi) : "l"(v));
}
__device__ __forceinline__ ull add2(ull a, ull b) {
    ull r; asm("add.rn.f32x2 %0, %1, %2;" : "=l"(r) : "l"(a), "l"(b)); return r;
}
__device__ __forceinline__ ull sub2(ull a, ull b) {
    ull r; asm("sub.rn.f32x2 %0, %1, %2;" : "=l"(r) : "l"(a), "l"(b)); return r;
}
__device__ __forceinline__ ull mul2(ull a, ull b) {
    ull r; asm("mul.rn.f32x2 %0, %1, %2;" : "=l"(r) : "l"(a), "l"(b)); return r;
}
__device__ __forceinline__ ull fma2(ull a, ull b, ull c) {
    ull r; asm("fma.rn.f32x2 %0, %1, %2, %3;" : "=l"(r) : "l"(a), "l"(b), "l"(c)); return r;
}

__global__ __launch_bounds__(NW * 32, 3)
void dyn_dense_kernel(const float* __restrict__ x, const float* __restrict__ ws,
                      const float* __restrict__ qs, const float* __restrict__ bias,
                      float* __restrict__ out)
{
    __shared__ float2 sx2[NW][SPAIR][32];          // 32 KB: first 16 steps as (t,t+1) pairs
    __shared__ float2 invc2[TLEN / 2];             //  2 KB: (1/(2p+1), 1/(2p+2))
    __shared__ float  sm_s[NW][32];                //  6 KB partials
    __shared__ float  sm_m[NW][32];
    __shared__ float  sm_q[NW][32];
    // total static smem: 40 KB -> no dynamic smem, no cudaFuncSetAttribute

    const int tid  = threadIdx.x;
    const int warp = tid >> 5;
    const int lane = tid & 31;

    if (tid < TLEN / 2)
        invc2[tid] = make_float2(1.0f / (float)(2 * tid + 1),
                                 1.0f / (float)(2 * tid + 2));

    // grid = B * (FDIM/32); block covers 32 consecutive f, all of T
    const int fblk = blockIdx.x & (FDIM / 32 - 1);
    const int b    = blockIdx.x >> 5;
    const int f    = fblk * 32 + lane;

    const size_t colbase = (size_t)b * TLEN * FDIM + (size_t)(warp * CHUNK) * FDIM + f;
    const float* p = x + colbase;

    // ---- Phase 1: load chunk ONCE; stage first 16 steps to smem as pairs,
    //      accumulate partials over all 32. Max identity 0.0f = Keras zero-init. ----
    float ps = 0.0f, pm = 0.0f, pq = 0.0f;
    {
        float xv[16];
        #pragma unroll
        for (int u = 0; u < 16; u++)
            xv[u] = __ldg(p + u * FDIM);           // 16 LDGs in flight
        #pragma unroll
        for (int u = 0; u < 16; u += 2) {
            sx2[warp][u >> 1][lane] = make_float2(xv[u], xv[u + 1]);  // STS.64
            ps += xv[u];  ps += xv[u + 1];
            pq  = fmaf(xv[u], xv[u], pq);
            pq  = fmaf(xv[u + 1], xv[u + 1], pq);
            pm  = fmaxf(pm, xv[u]);
            pm  = fmaxf(pm, xv[u + 1]);
        }
    }
    {
        float xw[16];
        #pragma unroll
        for (int u = 0; u < 16; u++)
            xw[u] = __ldg(p + (16 + u) * FDIM);
        #pragma unroll
        for (int u = 0; u < 16; u++) {
            ps += xw[u];
            pq  = fmaf(xw[u], xw[u], pq);
            pm  = fmaxf(pm, xw[u]);
        }
    }   // xw dead here; its lines stay L1/L2-resident for the phase-2 re-read
    if (warp < NW - 1) {                           // last warp's partials feed nobody
        sm_s[warp][lane] = ps;
        sm_m[warp][lane] = pm;
        sm_q[warp][lane] = pq;
    }
    __syncthreads();

    // ---- Phase 2: exclusive prefix over earlier chunks ----
    float s = 0.0f, m = 0.0f, ss = 0.0f;
    #pragma unroll
    for (int w = 0; w < NW - 1; w++) {
        if (w < warp) {
            s  += sm_s[w][lane];
            m   = fmaxf(m, sm_m[w][lane]);
            ss += sm_q[w][lane];
        }
    }

    // per-aggregation weights (AGGS = sum,max,mean,var,std), duplicated packed
    const float w0 = __ldg(ws + 0 * FDIM + f);
    const float w1 = __ldg(ws + 1 * FDIM + f);
    const float w2 = __ldg(ws + 2 * FDIM + f);
    const float w3 = __ldg(ws + 3 * FDIM + f);
    const float w4 = __ldg(ws + 4 * FDIM + f);
    const float q0 = __ldg(qs + 0 * FDIM + f);
    const float q1 = __ldg(qs + 1 * FDIM + f);
    // fold exact eps-correction into bias (z-chain uses w3*(var+eps))
    const float bz = fmaf(-w3, 1e-4f, __ldg(bias + f));

    const ull W0P = pack2(w0, w0);
    const ull W1P = pack2(w1, w1);
    const ull W2P = pack2(w2, w2);
    const ull W3P = pack2(w3, w3);
    const ull W4P = pack2(w4, w4);
    const ull Q0P = pack2(q0, q0);
    const ull Q1P = pack2(q1, q1);
    const ull BZP = pack2(bz, bz);
    const ull EPSP = pack2(1e-4f, 1e-4f);
    const ull TWOP = pack2(2.0f, 2.0f);

    const float c0 = (float)(warp * CHUNK);
    ull CPP = pack2(c0 + 1.0f, c0 + 2.0f);         // counts of the (t, t+1) pair

    float* o = out + colbase;
    const float2* icp = &invc2[warp * NPAIR];

    // one packed pair-step: serial state twice (exact), then packed z-chain
    auto pairstep = [&](float2 xp2, int sp) {
        const float s1  = s  + xp2.x;              // state after t
        const float ss1 = fmaf(xp2.x, xp2.x, ss);
        const float m1  = fmaxf(m, xp2.x);
        s  = s1 + xp2.y;                           // state after t+1
        ss = fmaf(xp2.y, xp2.y, ss1);
        m  = fmaxf(m1, xp2.y);

        const ull SP  = pack2(s1, s);
        const ull MP  = pack2(m1, m);
        const ull SSP = pack2(ss1, ss);
        const ull ICP = *(const ull*)&icp[sp];     // LDS.64 broadcast (1/c_t, 1/c_{t+1})

        const ull MEANP = mul2(SP, ICP);
        const ull T1P   = fma2(SSP, ICP, EPSP);    // ss/c + eps
        const ull VEPSP = sub2(T1P, mul2(MEANP, MEANP)); // var + eps

        float v0, v1; unpack2(VEPSP, v0, v1);
        const ull SDP = pack2(fast_sqrt(v0), fast_sqrt(v1));

        ull ZP = fma2(Q1P, CPP, Q0P);              // count polynomial
        ZP = fma2(ZP, CPP, BZP);                   // BZP holds eps fix
        ZP = fma2(W0P, SP,    ZP);
        ZP = fma2(W1P, MP,    ZP);
        ZP = fma2(W2P, MEANP, ZP);
        ZP = fma2(W3P, VEPSP, ZP);
        ZP = fma2(W4P, SDP,   ZP);
        CPP = add2(CPP, TWOP);

        float z0, z1; unpack2(ZP, z0, z1);
        o[(2 * sp)     * FDIM] = fast_tanh(z0);
        o[(2 * sp + 1) * FDIM] = fast_tanh(z1);
    };

    // prefetch first re-read pair (steps 16,17) — L1/L2-hot from phase 1
    const float* pr = p + 16 * FDIM;
    float2 nxt = make_float2(__ldg(pr), __ldg(pr + FDIM));

    // pairs 0..7 from smem (LDS.64)
    #pragma unroll
    for (int sp = 0; sp < SPAIR; sp++)
        pairstep(sx2[warp][sp][lane], sp);

    // pairs 8..15 re-read from global, one pair prefetched ahead
    #pragma unroll
    for (int g = 0; g < NPAIR - SPAIR; g++) {
        const float2 cur = nxt;
        if (g < NPAIR - SPAIR - 1) {
            const float* q = pr + 2 * (g + 1) * FDIM;
            nxt = make_float2(__ldg(q), __ldg(q + FDIM));
        }
        pairstep(cur, SPAIR + g);
    }
}

extern "C" void kernel_launch(void* const* d_in, const int* in_sizes, int n_in,
                              void* d_out, int out_size)
{
    const float* x    = (const float*)d_in[0];
    const float* ws   = (const float*)d_in[1];
    const float* qs   = (const float*)d_in[2];
    const float* bias = (const float*)d_in[3];
    float* out = (float*)d_out;

    const int grid = 32 * (FDIM / 32);   // B * 32 f-tiles = 1024 blocks
    dyn_dense_kernel<<<grid, NW * 32>>>(x, ws, qs, bias, out);
}

// round 15
// speedup vs baseline: 1.0625x; 1.0049x over previous
#include <cuda_runtime.h>
#include <cuda_bf16.h>
#include <cstdint>

#define TLEN  512
#define FDIM  1024
#define NW    16            // warps per block = time chunks
#define CHUNK (TLEN / NW)   // 32 timesteps per warp
#define NPAIR (CHUNK / 2)   // 16 (t,t+1) pairs per warp
#define SPAIR 8             // pairs staged in smem; rest re-read (L1/L2-hot)

typedef unsigned long long ull;

__device__ __forceinline__ float fast_sqrt(float a) {
    float r; asm("sqrt.approx.f32 %0, %1;" : "=f"(r) : "f"(a)); return r;
}
__device__ __forceinline__ float fast_tanh(float a) {
    float r; asm("tanh.approx.f32 %0, %1;" : "=f"(r) : "f"(a)); return r;
}
// ---- packed f32x2 (sm_100+) ----
__device__ __forceinline__ ull pack2(float lo, float hi) {
    ull r; asm("mov.b64 %0, {%1, %2};" : "=l"(r) : "f"(lo), "f"(hi)); return r;
}
__device__ __forceinline__ void unpack2(ull v, float& lo, float& hi) {
    asm("mov.b64 {%0, %1}, %2;" : "=f"(lo), "=f"(hi) : "l"(v));
}
__device__ __forceinline__ ull add2(ull a, ull b) {
    ull r; asm("add.rn.f32x2 %0, %1, %2;" : "=l"(r) : "l"(a), "l"(b)); return r;
}
__device__ __forceinline__ ull sub2(ull a, ull b) {
    ull r; asm("sub.rn.f32x2 %0, %1, %2;" : "=l"(r) : "l"(a), "l"(b)); return r;
}
__device__ __forceinline__ ull mul2(ull a, ull b) {
    ull r; asm("mul.rn.f32x2 %0, %1, %2;" : "=l"(r) : "l"(a), "l"(b)); return r;
}
__device__ __forceinline__ ull fma2(ull a, ull b, ull c) {
    ull r; asm("fma.rn.f32x2 %0, %1, %2, %3;" : "=l"(r) : "l"(a), "l"(b), "l"(c)); return r;
}

__global__ __launch_bounds__(NW * 32, 3)
void dyn_dense_kernel(const float* __restrict__ x, const float* __restrict__ ws,
                      const float* __restrict__ qs, const float* __restrict__ bias,
                      float* __restrict__ out)
{
    __shared__ float2 sx2[NW][SPAIR][32];          // 32 KB: first 16 steps as (t,t+1) pairs
    __shared__ float2 invc2[TLEN / 2];             //  2 KB: (1/(2p+1), 1/(2p+2))
    __shared__ float  sm_s[NW][32];                //  6 KB partials
    __shared__ float  sm_m[NW][32];
    __shared__ float  sm_q[NW][32];
    // total static smem: 40 KB (no dynamic smem path)

    const int tid  = threadIdx.x;
    const int warp = tid >> 5;
    const int lane = tid & 31;

    if (tid < TLEN / 2)
        invc2[tid] = make_float2(1.0f / (float)(2 * tid + 1),
                                 1.0f / (float)(2 * tid + 2));

    // grid = B * (FDIM/32); block covers 32 consecutive f, all of T
    const int fblk = blockIdx.x & (FDIM / 32 - 1);
    const int b    = blockIdx.x >> 5;
    const int f    = fblk * 32 + lane;

    const size_t colbase = (size_t)b * TLEN * FDIM + (size_t)(warp * CHUNK) * FDIM + f;
    const float* p = x + colbase;

    // ---- Phase 1: load chunk ONCE; stage first 16 steps to smem as pairs,
    //      accumulate partials over all 32. Max identity 0.0f = Keras zero-init. ----
    float ps = 0.0f, pm = 0.0f, pq = 0.0f;
    {
        float xv[16];
        #pragma unroll
        for (int u = 0; u < 16; u++)
            xv[u] = __ldg(p + u * FDIM);           // 16 LDGs in flight
        #pragma unroll
        for (int u = 0; u < 16; u += 2) {
            sx2[warp][u >> 1][lane] = make_float2(xv[u], xv[u + 1]);  // STS.64
            ps += xv[u];  ps += xv[u + 1];
            pq  = fmaf(xv[u], xv[u], pq);
            pq  = fmaf(xv[u + 1], xv[u + 1], pq);
            pm  = fmaxf(pm, xv[u]);
            pm  = fmaxf(pm, xv[u + 1]);
        }
    }
    {
        float xw[16];
        #pragma unroll
        for (int u = 0; u < 16; u++)
            xw[u] = __ldg(p + (16 + u) * FDIM);
        #pragma unroll
        for (int u = 0; u < 16; u++) {
            ps += xw[u];
            pq  = fmaf(xw[u], xw[u], pq);
            pm  = fmaxf(pm, xw[u]);
        }
    }   // xw dead; its lines stay L1/L2-resident for the phase-2 re-read
    if (warp < NW - 1) {                           // last warp's partials feed nobody
        sm_s[warp][lane] = ps;
        sm_m[warp][lane] = pm;
        sm_q[warp][lane] = pq;
    }
    __syncthreads();

    // ---- Phase 2: exclusive prefix over earlier chunks ----
    float s = 0.0f, m = 0.0f, ss = 0.0f;
    #pragma unroll
    for (int w = 0; w < NW - 1; w++) {
        if (w < warp) {
            s  += sm_s[w][lane];
            m   = fmaxf(m, sm_m[w][lane]);
            ss += sm_q[w][lane];
        }
    }

    // per-aggregation weights (AGGS = sum,max,mean,var,std), duplicated packed
    const float w0 = __ldg(ws + 0 * FDIM + f);
    const float w1 = __ldg(ws + 1 * FDIM + f);
    const float w2 = __ldg(ws + 2 * FDIM + f);
    const float w3 = __ldg(ws + 3 * FDIM + f);
    const float w4 = __ldg(ws + 4 * FDIM + f);
    const float q0 = __ldg(qs + 0 * FDIM + f);
    const float q1 = __ldg(qs + 1 * FDIM + f);
    // fold exact eps-correction into bias (z-chain uses w3*(var+eps))
    const float bz = fmaf(-w3, 1e-4f, __ldg(bias + f));

    const ull W0P = pack2(w0, w0);
    const ull W1P = pack2(w1, w1);
    const ull W2P = pack2(w2, w2);
    const ull W3P = pack2(w3, w3);
    const ull W4P = pack2(w4, w4);
    const ull Q0P = pack2(q0, q0);
    const ull Q1P = pack2(q1, q1);
    const ull BZP = pack2(bz, bz);
    const ull EPSP = pack2(1e-4f, 1e-4f);
    const ull TWOP = pack2(2.0f, 2.0f);

    const float c0 = (float)(warp * CHUNK);
    ull CPP = pack2(c0 + 1.0f, c0 + 2.0f);         // counts of the (t, t+1) pair

    float* o = out + colbase;
    const float2* icp = &invc2[warp * NPAIR];

    // one packed pair-step: serial state twice (exact), then packed z-chain
    auto pairstep = [&](float2 xp2, int sp) {
        const float s1  = s  + xp2.x;              // state after t
        const float ss1 = fmaf(xp2.x, xp2.x, ss);
        const float m1  = fmaxf(m, xp2.x);
        s  = s1 + xp2.y;                           // state after t+1
        ss = fmaf(xp2.y, xp2.y, ss1);
        m  = fmaxf(m1, xp2.y);

        const ull SP  = pack2(s1, s);
        const ull MP  = pack2(m1, m);
        const ull SSP = pack2(ss1, ss);
        const ull ICP = *(const ull*)&icp[sp];     // LDS.64 broadcast (1/c_t, 1/c_{t+1})

        const ull MEANP = mul2(SP, ICP);
        const ull T1P   = fma2(SSP, ICP, EPSP);    // ss/c + eps
        const ull VEPSP = sub2(T1P, mul2(MEANP, MEANP)); // var + eps

        float v0, v1; unpack2(VEPSP, v0, v1);
        const ull SDP = pack2(fast_sqrt(v0), fast_sqrt(v1));

        ull ZP = fma2(Q1P, CPP, Q0P);              // count polynomial
        ZP = fma2(ZP, CPP, BZP);                   // BZP holds eps fix
        ZP = fma2(W0P, SP,    ZP);
        ZP = fma2(W1P, MP,    ZP);
        ZP = fma2(W2P, MEANP, ZP);
        ZP = fma2(W3P, VEPSP, ZP);
        ZP = fma2(W4P, SDP,   ZP);
        CPP = add2(CPP, TWOP);

        float z0, z1; unpack2(ZP, z0, z1);
        // streaming stores: out is write-once; keep x resident in L1/L2
        __stcs(o + (2 * sp)     * FDIM, fast_tanh(z0));
        __stcs(o + (2 * sp + 1) * FDIM, fast_tanh(z1));
    };

    // prefetch first TWO re-read pairs (steps 16..19) — L1/L2-hot from phase 1
    const float* pr = p + 16 * FDIM;
    float2 nxt0 = make_float2(__ldg(pr),            __ldg(pr + FDIM));
    float2 nxt1 = make_float2(__ldg(pr + 2 * FDIM), __ldg(pr + 3 * FDIM));

    // pairs 0..7 from smem (LDS.64)
    #pragma unroll
    for (int sp = 0; sp < SPAIR; sp++)
        pairstep(sx2[warp][sp][lane], sp);

    // pairs 8..15 re-read from global with depth-2 rolling prefetch
    #pragma unroll
    for (int g = 0; g < NPAIR - SPAIR; g++) {
        const float2 cur = nxt0;
        nxt0 = nxt1;
        if (g < NPAIR - SPAIR - 2) {
            const float* q = pr + 2 * (g + 2) * FDIM;
            nxt1 = make_float2(__ldg(q), __ldg(q + FDIM));
        }
        pairstep(cur, SPAIR + g);
    }
}

extern "C" void kernel_launch(void* const* d_in, const int* in_sizes, int n_in,
                              void* d_out, int out_size)
{
    const float* x    = (const float*)d_in[0];
    const float* ws   = (const float*)d_in[1];
    const float* qs   = (const float*)d_in[2];
    const float* bias = (const float*)d_in[3];
    float* out = (float*)d_out;

    const int grid = 32 * (FDIM / 32);   // B * 32 f-tiles = 1024 blocks
    dyn_dense_kernel<<<grid, NW * 32>>>(x, ws, qs, bias, out);
}